// round 6
// baseline (speedup 1.0000x reference)
#include <cuda_runtime.h>
#include <math.h>

#define BROWS 256
#define FDIM  256
#define HDIM  1024
#define NX    (BROWS*FDIM)
#define NB    256
#define NT    512

// ---------------- persistent device state (no allocations) ----------------
__device__ float g_xbuf[2][NX];          // ping-pong x / x5
__device__ float g_h [BROWS*HDIM];       // hidden activations
__device__ float g_k [8][NX];            // RK stage ring (FSAL rotation)
__device__ float g_part[NB];             // per-block error partials
__device__ float g_t, g_dt;
__device__ int   g_par, g_kbase, g_fsal;
__device__ unsigned g_bar;               // cumulative grid-barrier counter

// ---------------- Dormand-Prince tableau ----------------------------------
__constant__ float c_A[7][6] = {
  {0,0,0,0,0,0},
  {(float)(1.0/5.0),0,0,0,0,0},
  {(float)(3.0/40.0),(float)(9.0/40.0),0,0,0,0},
  {(float)(44.0/45.0),(float)(-56.0/15.0),(float)(32.0/9.0),0,0,0},
  {(float)(19372.0/6561.0),(float)(-25360.0/2187.0),(float)(64448.0/6561.0),(float)(-212.0/729.0),0,0},
  {(float)(9017.0/3168.0),(float)(-355.0/33.0),(float)(46732.0/5247.0),(float)(49.0/176.0),(float)(-5103.0/18656.0),0},
  {(float)(35.0/384.0),0.0f,(float)(500.0/1113.0),(float)(125.0/192.0),(float)(-2187.0/6784.0),(float)(11.0/84.0)},
};
__constant__ float c_C[7]  = {0.f,0.2f,0.3f,0.8f,(float)(8.0/9.0),1.f,1.f};
__constant__ float c_B5[7] = {(float)(35.0/384.0),0.f,(float)(500.0/1113.0),(float)(125.0/192.0),
                              (float)(-2187.0/6784.0),(float)(11.0/84.0),0.f};
__constant__ float c_D[7]  = {
  (float)(35.0/384.0 - 5179.0/57600.0),
  0.f,
  (float)(500.0/1113.0 - 7571.0/16695.0),
  (float)(125.0/192.0 - 393.0/640.0),
  (float)(-2187.0/6784.0 + 92097.0/339200.0),
  (float)(11.0/84.0 - 187.0/2100.0),
  (float)(-1.0/40.0)};

// ---------------- shared-memory layout (floats) ----------------------------
#define SM_W1    0          // [256][32]  GEMM1 weight slice (k-major)
#define SM_W2    8192       // [1024][8]  GEMM2 weight slice (k-major)
#define SM_W1T   16384      // [32] time row of W1
#define SM_B1    16416      // [32] b1 slice
#define SM_B2    16448      // [8]  b2 slice
#define SM_SCR   16460      // [8320] scratch (xi slab / h chunks / reductions)
#define SM_FLOATS (SM_SCR + 8320)
#define SMEM_BYTES (SM_FLOATS * 4)

// ---------------- init: reset state every graph replay ---------------------
__global__ void k_init(const float* __restrict__ x0, float* __restrict__ out) {
  int i = blockIdx.x*blockDim.x + threadIdx.x;
  if (i < NX) { g_xbuf[0][i] = x0[i]; out[i] = x0[i]; }
  if (i == 0) { g_t = 0.f; g_dt = 0.05f; g_par = 0; g_kbase = 0; g_fsal = 0; g_bar = 0u; }
}

// ---------------- software grid barrier ------------------------------------
__device__ __forceinline__ void gridbar() {
  __syncthreads();
  if (threadIdx.x == 0) {
    __threadfence();
    unsigned gen = atomicAdd(&g_bar, 1u);
    unsigned target = gen - (gen % NB) + NB;
    unsigned v;
    do {
      asm volatile("ld.acquire.gpu.u32 %0, [%1];" : "=r"(v) : "l"(&g_bar) : "memory");
    } while ((int)(v - target) < 0);
    __threadfence();
  }
  __syncthreads();
}

// ---------------- persistent solver kernel ---------------------------------
__global__ void __launch_bounds__(NT, 2) k_ode(
    const float* __restrict__ W1, const float* __restrict__ b1,
    const float* __restrict__ W2, const float* __restrict__ b2,
    float* __restrict__ out)
{
  extern __shared__ float sm[];
  const int b = blockIdx.x, tid = threadIdx.x;

  const int bRm = (b >> 5) * 32;     // 32-row slab (8 slabs)
  const int bHn = (b & 31) * 32;     // GEMM1 h-column slice (32)
  const int bKn = (b & 31) * 8;      // GEMM2 k-column slice (8)

  // ---- prologue: stage weight slices into smem (persist across all iters) --
  for (int i = tid; i < 256*32; i += NT)
    sm[SM_W1 + i] = W1[(i >> 5)*HDIM + bHn + (i & 31)];
  for (int i = tid; i < 1024*8; i += NT)
    sm[SM_W2 + i] = W2[(i >> 3)*FDIM + bKn + (i & 7)];
  if (tid < 32) {
    sm[SM_W1T + tid] = W1[FDIM*HDIM + bHn + tid];
    sm[SM_B1  + tid] = b1[bHn + tid];
  }
  if (tid < 8) sm[SM_B2 + tid] = b2[bKn + tid];
  __syncthreads();

  float* sA = &sm[SM_SCR];

  for (int it = 0; it < 64; it++) {
    float t = *(volatile float*)&g_t;
    if (t >= 1.0f) break;                         // uniform across the grid
    float dt    = *(volatile float*)&g_dt;
    int   par   = *(volatile int*)&g_par;
    int   kbase = *(volatile int*)&g_kbase;
    int   fsal  = *(volatile int*)&g_fsal;
    const float* cur = g_xbuf[par];
    float*       nxt = g_xbuf[par ^ 1];
    float dt_c = fmaxf(fminf(dt, 1.0f - t), 0.0f);

    for (int s = fsal ? 1 : 0; s < 7; s++) {
      // ======== GEMM1: h = tanh(xi @ W1[:-1] + ts*W1[-1] + b1) ============
      // tile 32 rows x 32 cols; thread = (kz2, mg16 row-pairs, n2 16 col-pairs)
      {
        // build xi slab [32][260]
        {
          float ca[6];
          #pragma unroll
          for (int j = 0; j < 6; j++) ca[j] = dt_c * c_A[s][j];
          for (int i = tid; i < 32*256; i += NT) {
            int m = i >> 8, kk = i & 255;
            int gi = (bRm + m)*FDIM + kk;
            float v = cur[gi];
            for (int j = 0; j < s; j++) v = fmaf(ca[j], g_k[(kbase + j) & 7][gi], v);
            sA[m*260 + kk] = v;
          }
        }
        __syncthreads();

        const int kz = tid >> 8;          // K half (128 each)
        const int mg = (tid >> 4) & 15;   // row pair
        const int n2 = tid & 15;          // col pair
        float a00 = 0.f, a01 = 0.f, a10 = 0.f, a11 = 0.f;
        {
          const float* ap0 = &sA[(mg*2 + 0)*260 + kz*128];
          const float* ap1 = &sA[(mg*2 + 1)*260 + kz*128];
          const float* bp  = &sm[SM_W1 + (kz*128)*32 + n2*2];
          #pragma unroll 4
          for (int k = 0; k < 128; k += 4) {
            float4 x0 = *(const float4*)(ap0 + k);
            float4 x1 = *(const float4*)(ap1 + k);
            float2 w0 = *(const float2*)(bp + (k+0)*32);
            float2 w1 = *(const float2*)(bp + (k+1)*32);
            float2 w2 = *(const float2*)(bp + (k+2)*32);
            float2 w3 = *(const float2*)(bp + (k+3)*32);
            a00 = fmaf(x0.x, w0.x, a00); a01 = fmaf(x0.x, w0.y, a01);
            a10 = fmaf(x1.x, w0.x, a10); a11 = fmaf(x1.x, w0.y, a11);
            a00 = fmaf(x0.y, w1.x, a00); a01 = fmaf(x0.y, w1.y, a01);
            a10 = fmaf(x1.y, w1.x, a10); a11 = fmaf(x1.y, w1.y, a11);
            a00 = fmaf(x0.z, w2.x, a00); a01 = fmaf(x0.z, w2.y, a01);
            a10 = fmaf(x1.z, w2.x, a10); a11 = fmaf(x1.z, w2.y, a11);
            a00 = fmaf(x0.w, w3.x, a00); a01 = fmaf(x0.w, w3.y, a01);
            a10 = fmaf(x1.w, w3.x, a10); a11 = fmaf(x1.w, w3.y, a11);
          }
        }
        __syncthreads();                 // xi slab dead; reuse scratch
        const int idx = mg*16 + n2;      // 0..255
        if (kz == 1) {
          sA[idx*4 + 0] = a00; sA[idx*4 + 1] = a01;
          sA[idx*4 + 2] = a10; sA[idx*4 + 3] = a11;
        }
        __syncthreads();
        if (kz == 0) {
          float ts = t + c_C[s]*dt_c;
          a00 += sA[idx*4 + 0]; a01 += sA[idx*4 + 1];
          a10 += sA[idx*4 + 2]; a11 += sA[idx*4 + 3];
          float wt0 = sm[SM_W1T + n2*2], wt1 = sm[SM_W1T + n2*2 + 1];
          float bb0 = sm[SM_B1  + n2*2], bb1 = sm[SM_B1  + n2*2 + 1];
          float2 o0, o1;
          o0.x = tanhf(fmaf(ts, wt0, a00 + bb0));
          o0.y = tanhf(fmaf(ts, wt1, a01 + bb1));
          o1.x = tanhf(fmaf(ts, wt0, a10 + bb0));
          o1.y = tanhf(fmaf(ts, wt1, a11 + bb1));
          int row = (bRm + mg*2)*HDIM + bHn + n2*2;
          *(float2*)&g_h[row       ] = o0;
          *(float2*)&g_h[row + HDIM] = o1;
        }
      }
      gridbar();

      // ======== GEMM2: k_s = h @ W2 + b2 ==================================
      // tile 32 rows x 8 cols, 16-way K-split; thread = (kz16, row32)
      {
        const int row = tid & 31, kz = tid >> 5;   // kz: 16 chunks of 16k per 256-chunk
        float acc0=0.f,acc1=0.f,acc2=0.f,acc3=0.f,acc4=0.f,acc5=0.f,acc6=0.f,acc7=0.f;
        for (int c = 0; c < 4; c++) {
          // stage h chunk [32][257]
          for (int i = tid; i < 32*256; i += NT) {
            int m = i >> 8, kk = i & 255;
            sA[m*257 + kk] = g_h[(bRm + m)*HDIM + c*256 + kk];
          }
          __syncthreads();
          const float* ap = &sA[row*257 + kz*16];
          const float* bp = &sm[SM_W2 + (c*256 + kz*16)*8];
          #pragma unroll
          for (int k = 0; k < 16; k++) {
            float a = ap[k];
            float4 b0 = *(const float4*)(bp + k*8);
            float4 b1v = *(const float4*)(bp + k*8 + 4);
            acc0 = fmaf(a, b0.x,  acc0); acc1 = fmaf(a, b0.y,  acc1);
            acc2 = fmaf(a, b0.z,  acc2); acc3 = fmaf(a, b0.w,  acc3);
            acc4 = fmaf(a, b1v.x, acc4); acc5 = fmaf(a, b1v.y, acc5);
            acc6 = fmaf(a, b1v.z, acc6); acc7 = fmaf(a, b1v.w, acc7);
          }
          __syncthreads();
        }
        // deterministic K-split reduction via smem
        float* pp = &sA[kz*256 + row*8];
        pp[0]=acc0; pp[1]=acc1; pp[2]=acc2; pp[3]=acc3;
        pp[4]=acc4; pp[5]=acc5; pp[6]=acc6; pp[7]=acc7;
        __syncthreads();
        if (tid < 256) {
          float sum = 0.f;
          #pragma unroll
          for (int z = 0; z < 16; z++) sum += sA[z*256 + tid];
          int r = tid >> 3, cc = tid & 7;
          g_k[(kbase + s) & 7][(bRm + r)*FDIM + bKn + cc] = sum + sm[SM_B2 + cc];
        }
      }
      gridbar();
    }

    // ---- x5, err, per-block partial (1 element per low thread) -----------
    {
      float cb[7], cd[7];
      #pragma unroll
      for (int j = 0; j < 7; j++) { cb[j] = dt_c*c_B5[j]; cd[j] = dt_c*c_D[j]; }
      float rsq = 0.f;
      if (tid < 256) {
        int i = b*256 + tid;
        float x = cur[i], x5 = x, err = 0.f;
        #pragma unroll
        for (int j = 0; j < 7; j++) {
          float kv = g_k[(kbase + j) & 7][i];
          x5  = fmaf(cb[j], kv, x5);
          err = fmaf(cd[j], kv, err);
        }
        nxt[i] = x5;
        float scale = fmaf(1e-3f, fmaxf(fabsf(x), fabsf(x5)), 1e-4f);
        float r = err / scale;
        rsq = r*r;
      }
      sA[tid] = rsq;
      __syncthreads();
      #pragma unroll
      for (int st = 256; st > 0; st >>= 1) {
        if (tid < st) sA[tid] += sA[tid + st];
        __syncthreads();
      }
      if (tid == 0) g_part[b] = sA[0];
    }
    gridbar();

    // ---- finalize scalars (block 0) --------------------------------------
    if (b == 0) {
      sA[tid] = (tid < NB) ? g_part[tid] : 0.f;
      __syncthreads();
      #pragma unroll
      for (int st = 256; st > 0; st >>= 1) {
        if (tid < st) sA[tid] += sA[tid + st];
        __syncthreads();
      }
      if (tid == 0) {
        float err_norm = sqrtf(sA[0] * (1.0f/(float)NX));
        int accept = (err_norm <= 1.0f);
        float factor = 0.9f * powf(err_norm + 1e-10f, -0.2f);
        factor = fminf(fmaxf(factor, 0.2f), 5.0f);
        if (accept) {
          g_t = t + dt_c;
          g_par = par ^ 1;
          g_kbase = (kbase + 6) & 7;   // FSAL: new k0 slot = old k6 slot
          g_fsal = 1;
        } else {
          g_fsal = 0;
        }
        g_dt = dt_c * factor;
      }
    }
    gridbar();
  }

  // ---- write final trajectory row ----------------------------------------
  if (tid < 256) {
    int par = *(volatile int*)&g_par;
    int i = b*256 + tid;
    out[NX + i] = g_xbuf[par][i];
  }
}

extern "C" void kernel_launch(void* const* d_in, const int* in_sizes, int n_in,
                              void* d_out, int out_size) {
  const float* x0 = (const float*)d_in[0];
  const float* W1 = (const float*)d_in[1];
  const float* b1 = (const float*)d_in[2];
  const float* W2 = (const float*)d_in[3];
  const float* b2 = (const float*)d_in[4];
  float* out = (float*)d_out;

  cudaFuncSetAttribute(k_ode, cudaFuncAttributeMaxDynamicSharedMemorySize, SMEM_BYTES);
  k_init<<<NB, NT>>>(x0, out);
  k_ode<<<NB, NT, SMEM_BYTES>>>(W1, b1, W2, b2, out);
}

// round 10
// speedup vs baseline: 2.0775x; 2.0775x over previous
#include <cuda_runtime.h>
#include <math.h>

#define FDIM  256
#define HDIM  1024
#define NX    65536
#define NB    128
#define NT    512

// ---------------- persistent device state (no allocations) ----------------
__device__ float g_xbuf[2][NX];          // ping-pong x / x5
__device__ float g_k[8][NX];             // RK stage ring (FSAL rotation)
__device__ float g_p[NB*32*256];         // GEMM2 partials [slab][slice][32][256]
__device__ float g_part[NB];             // per-block error partials
__device__ unsigned g_bar;               // cumulative grid-barrier counter

// ---------------- Dormand-Prince tableau ----------------------------------
__constant__ float c_A[7][6] = {
  {0,0,0,0,0,0},
  {(float)(1.0/5.0),0,0,0,0,0},
  {(float)(3.0/40.0),(float)(9.0/40.0),0,0,0,0},
  {(float)(44.0/45.0),(float)(-56.0/15.0),(float)(32.0/9.0),0,0,0},
  {(float)(19372.0/6561.0),(float)(-25360.0/2187.0),(float)(64448.0/6561.0),(float)(-212.0/729.0),0,0},
  {(float)(9017.0/3168.0),(float)(-355.0/33.0),(float)(46732.0/5247.0),(float)(49.0/176.0),(float)(-5103.0/18656.0),0},
  {(float)(35.0/384.0),0.0f,(float)(500.0/1113.0),(float)(125.0/192.0),(float)(-2187.0/6784.0),(float)(11.0/84.0)},
};
__constant__ float c_C[7]  = {0.f,0.2f,0.3f,0.8f,(float)(8.0/9.0),1.f,1.f};
__constant__ float c_B5[7] = {(float)(35.0/384.0),0.f,(float)(500.0/1113.0),(float)(125.0/192.0),
                              (float)(-2187.0/6784.0),(float)(11.0/84.0),0.f};
__constant__ float c_D[7]  = {
  (float)(35.0/384.0 - 5179.0/57600.0),
  0.f,
  (float)(500.0/1113.0 - 7571.0/16695.0),
  (float)(125.0/192.0 - 393.0/640.0),
  (float)(-2187.0/6784.0 + 92097.0/339200.0),
  (float)(11.0/84.0 - 187.0/2100.0),
  (float)(-1.0/40.0)};

// ---------------- shared-memory layout (floats) ----------------------------
#define OFF_W1   0        // [256][64]  W1 column slice, k-major
#define OFF_W2   16384    // [64][256]  W2 row slice (this block's h-cols)
#define OFF_W1T  32768    // [64]
#define OFF_B1   32832    // [64]
#define OFF_B2   32896    // [256] (full b2)
#define OFF_SA   33152    // [8320] xi slab (stride 260) / scratch
#define OFF_HB   41472    // [2048] h_blk [32][64]
#define SM_FLOATS 43520
#define SMEM_BYTES (SM_FLOATS*4)

// ---------------- init: reset state every graph replay ---------------------
__global__ void k_init(const float* __restrict__ x0, float* __restrict__ out) {
  int i = blockIdx.x*blockDim.x + threadIdx.x;
  g_xbuf[0][i] = x0[i];
  out[i] = x0[i];
  if (i == 0) g_bar = 0u;
}

// ---------------- software grid barrier ------------------------------------
__device__ __forceinline__ void gridbar() {
  __syncthreads();
  if (threadIdx.x == 0) {
    __threadfence();
    unsigned gen = atomicAdd(&g_bar, 1u);
    unsigned target = gen - (gen % NB) + NB;
    unsigned v;
    do {
      asm volatile("ld.acquire.gpu.u32 %0, [%1];" : "=r"(v) : "l"(&g_bar) : "memory");
    } while ((int)(v - target) < 0);
    __threadfence();
  }
  __syncthreads();
}

// ---------------- persistent solver kernel ---------------------------------
__global__ void __launch_bounds__(NT, 1) k_ode(
    const float* __restrict__ W1, const float* __restrict__ b1,
    const float* __restrict__ W2, const float* __restrict__ b2,
    float* __restrict__ out)
{
  extern __shared__ float sm[];
  const int b = blockIdx.x, tid = threadIdx.x;
  const int slab = b >> 4, slice = b & 15;
  const int bHn = slice * 64;

  float* W1s = sm + OFF_W1;
  float* W2s = sm + OFF_W2;
  float* w1t = sm + OFF_W1T;
  float* b1s = sm + OFF_B1;
  float* b2s = sm + OFF_B2;
  float* sA  = sm + OFF_SA;
  float* hB  = sm + OFF_HB;

  // ---- prologue: weights resident in SMEM for the whole solve -------------
  for (int i = tid; i < 16384; i += NT) W1s[i] = W1[(i >> 6)*HDIM + bHn + (i & 63)];
  for (int i = tid; i < 16384; i += NT) W2s[i] = W2[(bHn + (i >> 8))*FDIM + (i & 255)];
  if (tid < 64) { w1t[tid] = W1[FDIM*HDIM + bHn + tid]; b1s[tid] = b1[bHn + tid]; }
  if (tid < 256) b2s[tid] = b2[tid];
  __syncthreads();

  const int wid = tid >> 5, lane = tid & 31;

  // block-local solver scalars (identical across blocks by construction)
  float t = 0.f, dt = 0.05f;
  int par = 0, kbase = 0, fsal = 0;

  for (int it = 0; it < 64; it++) {
    if (t >= 1.0f) break;                         // uniform across grid
    float dt_c = fmaxf(fminf(dt, 1.0f - t), 0.0f);
    const float* cur = g_xbuf[par];
    float*       nxt = g_xbuf[par ^ 1];

    for (int s = fsal ? 1 : 0; s < 7; s++) {
      // ======== xi slab build: [32][256] into sA (stride 260) =============
      {
        float ca[6];
        #pragma unroll
        for (int j = 0; j < 6; j++) ca[j] = dt_c * c_A[s][j];
        #pragma unroll
        for (int c4 = 0; c4 < 4; c4++) {
          int i4 = c4*2048 + tid*4;
          int m = i4 >> 8, kk = i4 & 255;
          int gi = (slab*32 + m)*FDIM + kk;
          float4 v = *(const float4*)&cur[gi];
          for (int j = 0; j < s; j++) {
            float4 kv = *(const float4*)&g_k[(kbase + j) & 7][gi];
            v.x = fmaf(ca[j], kv.x, v.x);
            v.y = fmaf(ca[j], kv.y, v.y);
            v.z = fmaf(ca[j], kv.z, v.z);
            v.w = fmaf(ca[j], kv.w, v.w);
          }
          *(float4*)&sA[m*260 + kk] = v;
        }
      }
      __syncthreads();

      // ======== GEMM1: h_blk = tanh(xi @ W1s + ts*w1t + b1s) ==============
      // warp = 4 rows x 64 cols, K-split 2 (kz); lane = 4 rows x 2 cols
      {
        const int kz = wid & 1, rg = wid >> 1;
        float acc00=0,acc01=0,acc10=0,acc11=0,acc20=0,acc21=0,acc30=0,acc31=0;
        const float* Ap0 = &sA[(rg*4 + 0)*260 + kz*128];
        const float* Ap1 = &sA[(rg*4 + 1)*260 + kz*128];
        const float* Ap2 = &sA[(rg*4 + 2)*260 + kz*128];
        const float* Ap3 = &sA[(rg*4 + 3)*260 + kz*128];
        const float* Bp  = &W1s[(kz*128)*64 + lane*2];
        #pragma unroll 2
        for (int k = 0; k < 128; k += 4) {
          float a0[4], a1[4], a2[4], a3[4];
          *(float4*)a0 = *(const float4*)(Ap0 + k);
          *(float4*)a1 = *(const float4*)(Ap1 + k);
          *(float4*)a2 = *(const float4*)(Ap2 + k);
          *(float4*)a3 = *(const float4*)(Ap3 + k);
          #pragma unroll
          for (int q = 0; q < 4; q++) {
            float2 w = *(const float2*)(Bp + (k + q)*64);
            acc00 = fmaf(a0[q], w.x, acc00); acc01 = fmaf(a0[q], w.y, acc01);
            acc10 = fmaf(a1[q], w.x, acc10); acc11 = fmaf(a1[q], w.y, acc11);
            acc20 = fmaf(a2[q], w.x, acc20); acc21 = fmaf(a2[q], w.y, acc21);
            acc30 = fmaf(a3[q], w.x, acc30); acc31 = fmaf(a3[q], w.y, acc31);
          }
        }
        __syncthreads();                 // xi dead; sA reused as combine scratch
        float* cp = &sA[(rg*32 + lane)*8];
        if (kz) {
          cp[0]=acc00; cp[1]=acc01; cp[2]=acc10; cp[3]=acc11;
          cp[4]=acc20; cp[5]=acc21; cp[6]=acc30; cp[7]=acc31;
        }
        __syncthreads();
        if (!kz) {
          float ts = t + c_C[s]*dt_c;
          float wt0 = w1t[lane*2], wt1 = w1t[lane*2 + 1];
          float bb0 = b1s[lane*2], bb1 = b1s[lane*2 + 1];
          float* hp = &hB[(rg*4)*64 + lane*2];
          hp[0*64 + 0] = tanhf(fmaf(ts, wt0, (acc00 + cp[0]) + bb0));
          hp[0*64 + 1] = tanhf(fmaf(ts, wt1, (acc01 + cp[1]) + bb1));
          hp[1*64 + 0] = tanhf(fmaf(ts, wt0, (acc10 + cp[2]) + bb0));
          hp[1*64 + 1] = tanhf(fmaf(ts, wt1, (acc11 + cp[3]) + bb1));
          hp[2*64 + 0] = tanhf(fmaf(ts, wt0, (acc20 + cp[4]) + bb0));
          hp[2*64 + 1] = tanhf(fmaf(ts, wt1, (acc21 + cp[5]) + bb1));
          hp[3*64 + 0] = tanhf(fmaf(ts, wt0, (acc30 + cp[6]) + bb0));
          hp[3*64 + 1] = tanhf(fmaf(ts, wt1, (acc31 + cp[7]) + bb1));
        }
      }
      __syncthreads();

      // ======== GEMM2 partial: p[32][256] = h_blk @ W2s ===================
      // warp = 4 rows x 128 cols (ch half); lane = 4 rows x 4 cols
      {
        const int rg2 = wid >> 1, ch = wid & 1;
        float4 acc0 = {0,0,0,0}, acc1 = {0,0,0,0}, acc2 = {0,0,0,0}, acc3 = {0,0,0,0};
        const float* Ap0 = &hB[(rg2*4 + 0)*64];
        const float* Ap1 = &hB[(rg2*4 + 1)*64];
        const float* Ap2 = &hB[(rg2*4 + 2)*64];
        const float* Ap3 = &hB[(rg2*4 + 3)*64];
        const float* Bp  = &W2s[ch*128 + lane*4];
        #pragma unroll 2
        for (int k = 0; k < 64; k += 4) {
          float a0[4], a1[4], a2[4], a3[4];
          *(float4*)a0 = *(const float4*)(Ap0 + k);
          *(float4*)a1 = *(const float4*)(Ap1 + k);
          *(float4*)a2 = *(const float4*)(Ap2 + k);
          *(float4*)a3 = *(const float4*)(Ap3 + k);
          #pragma unroll
          for (int q = 0; q < 4; q++) {
            float4 w = *(const float4*)(Bp + (k + q)*256);
            acc0.x = fmaf(a0[q], w.x, acc0.x); acc0.y = fmaf(a0[q], w.y, acc0.y);
            acc0.z = fmaf(a0[q], w.z, acc0.z); acc0.w = fmaf(a0[q], w.w, acc0.w);
            acc1.x = fmaf(a1[q], w.x, acc1.x); acc1.y = fmaf(a1[q], w.y, acc1.y);
            acc1.z = fmaf(a1[q], w.z, acc1.z); acc1.w = fmaf(a1[q], w.w, acc1.w);
            acc2.x = fmaf(a2[q], w.x, acc2.x); acc2.y = fmaf(a2[q], w.y, acc2.y);
            acc2.z = fmaf(a2[q], w.z, acc2.z); acc2.w = fmaf(a2[q], w.w, acc2.w);
            acc3.x = fmaf(a3[q], w.x, acc3.x); acc3.y = fmaf(a3[q], w.y, acc3.y);
            acc3.z = fmaf(a3[q], w.z, acc3.z); acc3.w = fmaf(a3[q], w.w, acc3.w);
          }
        }
        float* pb = &g_p[(b*32 + rg2*4)*256 + ch*128 + lane*4];
        *(float4*)&pb[0*256] = acc0;
        *(float4*)&pb[1*256] = acc1;
        *(float4*)&pb[2*256] = acc2;
        *(float4*)&pb[3*256] = acc3;
      }
      gridbar();

      // ======== reduce partials -> k_s (each block: its 512 elements) =====
      {
        const int idL = slice*512 + tid;      // 0..8191 within slab
        const float* pp = &g_p[slab*16*8192 + idL];
        float sum = 0.f;
        #pragma unroll
        for (int sl = 0; sl < 16; sl++) sum += pp[sl*8192];
        sum += b2s[idL & 255];
        const int gi = slab*8192 + idL;

        if (s < 6) {
          g_k[(kbase + s) & 7][gi] = sum;
          gridbar();
        } else {
          // stage-6 fused with x5/err (k6 = sum, consumed in-register)
          g_k[(kbase + 6) & 7][gi] = sum;      // FSAL slot for next iteration
          float cb[7], cd[7];
          #pragma unroll
          for (int j = 0; j < 7; j++) { cb[j] = dt_c*c_B5[j]; cd[j] = dt_c*c_D[j]; }
          float x = cur[gi], x5 = x, err = 0.f;
          #pragma unroll
          for (int j = 0; j < 6; j++) {
            float kv = g_k[(kbase + j) & 7][gi];
            x5  = fmaf(cb[j], kv, x5);
            err = fmaf(cd[j], kv, err);
          }
          x5  = fmaf(cb[6], sum, x5);
          err = fmaf(cd[6], sum, err);
          nxt[gi] = x5;
          float scale = fmaf(1e-3f, fmaxf(fabsf(x), fabsf(x5)), 1e-4f);
          float r = err / scale;
          sA[tid] = r*r;
          __syncthreads();
          #pragma unroll
          for (int st = 256; st > 0; st >>= 1) {
            if (tid < st) sA[tid] += sA[tid + st];
            __syncthreads();
          }
          if (tid == 0) g_part[b] = sA[0];
        }
      }
    }
    gridbar();

    // ======== finalize (replicated in every block, identical fp) ==========
    {
      if (tid < NB) sA[tid] = g_part[tid];
      __syncthreads();
      #pragma unroll
      for (int st = 64; st > 0; st >>= 1) {
        if (tid < st) sA[tid] += sA[tid + st];
        __syncthreads();
      }
      float err_norm = sqrtf(sA[0] * (1.0f/(float)NX));
      __syncthreads();                          // protect sA[0] before reuse
      int accept = (err_norm <= 1.0f);
      float factor = 0.9f * powf(err_norm + 1e-10f, -0.2f);
      factor = fminf(fmaxf(factor, 0.2f), 5.0f);
      if (accept) { t = t + dt_c; par ^= 1; kbase = (kbase + 6) & 7; }
      dt = dt_c * factor;
      fsal = 1;   // k0 stays valid on reject too (x, t unchanged)
    }
  }

  // ---- write final trajectory row ----------------------------------------
  {
    int gi = slab*8192 + slice*512 + tid;
    out[NX + gi] = g_xbuf[par][gi];
  }
}

extern "C" void kernel_launch(void* const* d_in, const int* in_sizes, int n_in,
                              void* d_out, int out_size) {
  const float* x0 = (const float*)d_in[0];
  const float* W1 = (const float*)d_in[1];
  const float* b1 = (const float*)d_in[2];
  const float* W2 = (const float*)d_in[3];
  const float* b2 = (const float*)d_in[4];
  float* out = (float*)d_out;

  cudaFuncSetAttribute(k_ode, cudaFuncAttributeMaxDynamicSharedMemorySize, SMEM_BYTES);
  k_init<<<NB, NT>>>(x0, out);
  k_ode<<<NB, NT, SMEM_BYTES>>>(W1, b1, W2, b2, out);
}

// round 11
// speedup vs baseline: 2.2863x; 1.1005x over previous
#include <cuda_runtime.h>
#include <math.h>

typedef unsigned long long u64t;

#define FDIM  256
#define HDIM  1024
#define NX    65536
#define NB    128
#define NT    512

// ---------------- persistent device state (no allocations) ----------------
__device__ float g_xbuf[2][NX];          // ping-pong x / x5
__device__ float g_k[8][NX];             // RK stage ring (FSAL rotation)
__device__ float g_p[NB*32*256];         // GEMM2 partials [slab][slice][32][256]
__device__ float g_part[NB];             // per-block error partials
__device__ unsigned g_bar;               // cumulative grid-barrier counter

// ---------------- Dormand-Prince tableau ----------------------------------
__constant__ float c_A[7][6] = {
  {0,0,0,0,0,0},
  {(float)(1.0/5.0),0,0,0,0,0},
  {(float)(3.0/40.0),(float)(9.0/40.0),0,0,0,0},
  {(float)(44.0/45.0),(float)(-56.0/15.0),(float)(32.0/9.0),0,0,0},
  {(float)(19372.0/6561.0),(float)(-25360.0/2187.0),(float)(64448.0/6561.0),(float)(-212.0/729.0),0,0},
  {(float)(9017.0/3168.0),(float)(-355.0/33.0),(float)(46732.0/5247.0),(float)(49.0/176.0),(float)(-5103.0/18656.0),0},
  {(float)(35.0/384.0),0.0f,(float)(500.0/1113.0),(float)(125.0/192.0),(float)(-2187.0/6784.0),(float)(11.0/84.0)},
};
__constant__ float c_C[7]  = {0.f,0.2f,0.3f,0.8f,(float)(8.0/9.0),1.f,1.f};
__constant__ float c_B5[7] = {(float)(35.0/384.0),0.f,(float)(500.0/1113.0),(float)(125.0/192.0),
                              (float)(-2187.0/6784.0),(float)(11.0/84.0),0.f};
__constant__ float c_D[7]  = {
  (float)(35.0/384.0 - 5179.0/57600.0),
  0.f,
  (float)(500.0/1113.0 - 7571.0/16695.0),
  (float)(125.0/192.0 - 393.0/640.0),
  (float)(-2187.0/6784.0 + 92097.0/339200.0),
  (float)(11.0/84.0 - 187.0/2100.0),
  (float)(-1.0/40.0)};

// ---------------- shared-memory layout (floats) ----------------------------
#define OFF_W1T  0                      // [64][258]  W1 slice, TRANSPOSED (col-major, k contig)
#define OFF_W2T  (64*258)               // [256][66]  W2 slice, TRANSPOSED
#define OFF_W1TM (OFF_W2T + 256*66)     // [64] time row
#define OFF_B1   (OFF_W1TM + 64)        // [64]
#define OFF_B2   (OFF_B1 + 64)          // [256]
#define OFF_SA   (OFF_B2 + 256)         // [8320] xi slab [32][260] / scratch
#define OFF_HB   (OFF_SA + 8320)        // [32][68] h_blk (padded)
#define SM_FLOATS (OFF_HB + 32*68)
#define SMEM_BYTES (SM_FLOATS*4)

// ---------------- packed f32x2 FMA (sm_100+ PTX) ---------------------------
__device__ __forceinline__ u64t f2fma(u64t a, u64t b, u64t c) {
  u64t d;
  asm("fma.rn.f32x2 %0, %1, %2, %3;" : "=l"(d) : "l"(a), "l"(b), "l"(c));
  return d;
}
__device__ __forceinline__ float f2fold(u64t v) {
  union { u64t u; float2 f; } cv; cv.u = v;
  return cv.f.x + cv.f.y;
}

// ---------------- init: reset state every graph replay ---------------------
__global__ void k_init(const float* __restrict__ x0, float* __restrict__ out) {
  int i = blockIdx.x*blockDim.x + threadIdx.x;
  g_xbuf[0][i] = x0[i];
  out[i] = x0[i];
  if (i == 0) g_bar = 0u;
}

// ---------------- software grid barrier ------------------------------------
__device__ __forceinline__ void gridbar() {
  __syncthreads();
  if (threadIdx.x == 0) {
    __threadfence();
    unsigned gen = atomicAdd(&g_bar, 1u);
    unsigned target = gen - (gen % NB) + NB;
    unsigned v;
    do {
      asm volatile("ld.acquire.gpu.u32 %0, [%1];" : "=r"(v) : "l"(&g_bar) : "memory");
    } while ((int)(v - target) < 0);
    __threadfence();
  }
  __syncthreads();
}

// ---------------- persistent solver kernel ---------------------------------
__global__ void __launch_bounds__(NT, 1) k_ode(
    const float* __restrict__ W1, const float* __restrict__ b1,
    const float* __restrict__ W2, const float* __restrict__ b2,
    float* __restrict__ out)
{
  extern __shared__ float sm[];
  const int b = blockIdx.x, tid = threadIdx.x;
  const int slab = b >> 4, slice = b & 15;
  const int bHn = slice * 64;

  float* W1T = sm + OFF_W1T;
  float* W2T = sm + OFF_W2T;
  float* w1t = sm + OFF_W1TM;
  float* b1s = sm + OFF_B1;
  float* b2s = sm + OFF_B2;
  float* sA  = sm + OFF_SA;
  float* hB  = sm + OFF_HB;

  // ---- prologue: weights resident (transposed) in SMEM ---------------------
  for (int i = tid; i < 64*256; i += NT) {       // i = k*64 + c (coalesced LDG)
    int k = i >> 6, c = i & 63;
    W1T[c*258 + k] = W1[k*HDIM + bHn + c];
  }
  for (int i = tid; i < 64*256; i += NT) {       // i = k*256 + c (coalesced LDG)
    int k = i >> 8, c = i & 255;
    W2T[c*66 + k] = W2[(bHn + k)*FDIM + c];
  }
  if (tid < 64) { w1t[tid] = W1[FDIM*HDIM + bHn + tid]; b1s[tid] = b1[bHn + tid]; }
  if (tid < 256) b2s[tid] = b2[tid];
  __syncthreads();

  const int wid = tid >> 5, lane = tid & 32-1;
  const int rs = lane >> 4, cg = lane & 15;

  // block-local solver scalars (identical across blocks by construction)
  float t = 0.f, dt = 0.05f;
  int par = 0, kbase = 0, fsal = 0;

  for (int it = 0; it < 64; it++) {
    if (t >= 1.0f) break;                         // uniform across grid
    float dt_c = fmaxf(fminf(dt, 1.0f - t), 0.0f);
    const float* cur = g_xbuf[par];
    float*       nxt = g_xbuf[par ^ 1];

    for (int s = fsal ? 1 : 0; s < 7; s++) {
      // ======== xi slab build: [32][260] into sA ==========================
      {
        float ca[6];
        #pragma unroll
        for (int j = 0; j < 6; j++) ca[j] = dt_c * c_A[s][j];
        #pragma unroll
        for (int c4 = 0; c4 < 4; c4++) {
          int i4 = c4*2048 + tid*4;
          int m = i4 >> 8, kk = i4 & 255;
          int gi = (slab*32 + m)*FDIM + kk;
          float4 v = *(const float4*)&cur[gi];
          for (int j = 0; j < s; j++) {
            float4 kv = *(const float4*)&g_k[(kbase + j) & 7][gi];
            v.x = fmaf(ca[j], kv.x, v.x);
            v.y = fmaf(ca[j], kv.y, v.y);
            v.z = fmaf(ca[j], kv.z, v.z);
            v.w = fmaf(ca[j], kv.w, v.w);
          }
          *(float4*)&sA[m*260 + kk] = v;
        }
      }
      __syncthreads();

      // ======== GEMM1: h_blk = tanh(xi @ W1slice), f32x2 packed ===========
      // warp: kz (K-split 4) x rg; thread: 4 rows x 4 cols
      {
        const int kz = wid & 3, rg = wid >> 2;
        const int r0 = rg*8 + rs*4;
        const float* A0 = &sA[(r0+0)*260 + kz*64];
        const float* A1 = &sA[(r0+1)*260 + kz*64];
        const float* A2 = &sA[(r0+2)*260 + kz*64];
        const float* A3 = &sA[(r0+3)*260 + kz*64];
        const float* B0 = &W1T[(cg+ 0)*258 + kz*64];
        const float* B1p= &W1T[(cg+16)*258 + kz*64];
        const float* B2p= &W1T[(cg+32)*258 + kz*64];
        const float* B3p= &W1T[(cg+48)*258 + kz*64];
        u64t acc[4][4];
        #pragma unroll
        for (int r = 0; r < 4; r++)
          #pragma unroll
          for (int i = 0; i < 4; i++) acc[r][i] = 0ULL;

        #pragma unroll 4
        for (int k = 0; k < 64; k += 4) {
          union { float4 f; u64t u[2]; } a0,a1,a2,a3;
          a0.f = *(const float4*)(A0+k);
          a1.f = *(const float4*)(A1+k);
          a2.f = *(const float4*)(A2+k);
          a3.f = *(const float4*)(A3+k);
          #pragma unroll
          for (int p = 0; p < 2; p++) {
            u64t w0 = *(const u64t*)(B0 +k+2*p);
            u64t w1 = *(const u64t*)(B1p+k+2*p);
            u64t w2 = *(const u64t*)(B2p+k+2*p);
            u64t w3 = *(const u64t*)(B3p+k+2*p);
            acc[0][0]=f2fma(a0.u[p],w0,acc[0][0]); acc[0][1]=f2fma(a0.u[p],w1,acc[0][1]);
            acc[0][2]=f2fma(a0.u[p],w2,acc[0][2]); acc[0][3]=f2fma(a0.u[p],w3,acc[0][3]);
            acc[1][0]=f2fma(a1.u[p],w0,acc[1][0]); acc[1][1]=f2fma(a1.u[p],w1,acc[1][1]);
            acc[1][2]=f2fma(a1.u[p],w2,acc[1][2]); acc[1][3]=f2fma(a1.u[p],w3,acc[1][3]);
            acc[2][0]=f2fma(a2.u[p],w0,acc[2][0]); acc[2][1]=f2fma(a2.u[p],w1,acc[2][1]);
            acc[2][2]=f2fma(a2.u[p],w2,acc[2][2]); acc[2][3]=f2fma(a2.u[p],w3,acc[2][3]);
            acc[3][0]=f2fma(a3.u[p],w0,acc[3][0]); acc[3][1]=f2fma(a3.u[p],w1,acc[3][1]);
            acc[3][2]=f2fma(a3.u[p],w2,acc[3][2]); acc[3][3]=f2fma(a3.u[p],w3,acc[3][3]);
          }
        }
        __syncthreads();                 // xi dead; reuse sA for kz partials
        #pragma unroll
        for (int r = 0; r < 4; r++)
          #pragma unroll
          for (int i = 0; i < 4; i++)
            sA[kz*2048 + (r0+r)*64 + cg + 16*i] = f2fold(acc[r][i]);
        __syncthreads();
        // finalize 4 h outputs per thread (fixed kz order, parallel tanh)
        {
          float ts = t + c_C[s]*dt_c;
          int o = tid*4;
          int row = o >> 6, col = o & 63;
          float4 s0 = *(const float4*)&sA[0*2048 + o];
          float4 s1 = *(const float4*)&sA[1*2048 + o];
          float4 s2 = *(const float4*)&sA[2*2048 + o];
          float4 s3 = *(const float4*)&sA[3*2048 + o];
          float v0 = ((s0.x + s1.x) + s2.x) + s3.x;
          float v1 = ((s0.y + s1.y) + s2.y) + s3.y;
          float v2 = ((s0.z + s1.z) + s2.z) + s3.z;
          float v3 = ((s0.w + s1.w) + s2.w) + s3.w;
          float* hp = &hB[row*68 + col];
          hp[0] = tanhf(fmaf(ts, w1t[col+0], v0 + b1s[col+0]));
          hp[1] = tanhf(fmaf(ts, w1t[col+1], v1 + b1s[col+1]));
          hp[2] = tanhf(fmaf(ts, w1t[col+2], v2 + b1s[col+2]));
          hp[3] = tanhf(fmaf(ts, w1t[col+3], v3 + b1s[col+3]));
        }
      }
      __syncthreads();

      // ======== GEMM2 partial: p = h_blk @ W2slice, f32x2 packed ==========
      // warp: wr x wc; thread: 4 rows x 4 cols, full K=64
      {
        const int wr = wid >> 2, wc = wid & 3;
        const int r0 = wr*8 + rs*4;
        const float* A0 = &hB[(r0+0)*68];
        const float* A1 = &hB[(r0+1)*68];
        const float* A2 = &hB[(r0+2)*68];
        const float* A3 = &hB[(r0+3)*68];
        const float* B0 = &W2T[(wc*64 + cg +  0)*66];
        const float* B1p= &W2T[(wc*64 + cg + 16)*66];
        const float* B2p= &W2T[(wc*64 + cg + 32)*66];
        const float* B3p= &W2T[(wc*64 + cg + 48)*66];
        u64t acc[4][4];
        #pragma unroll
        for (int r = 0; r < 4; r++)
          #pragma unroll
          for (int i = 0; i < 4; i++) acc[r][i] = 0ULL;

        #pragma unroll 4
        for (int k = 0; k < 64; k += 4) {
          union { float4 f; u64t u[2]; } a0,a1,a2,a3;
          a0.f = *(const float4*)(A0+k);
          a1.f = *(const float4*)(A1+k);
          a2.f = *(const float4*)(A2+k);
          a3.f = *(const float4*)(A3+k);
          #pragma unroll
          for (int p = 0; p < 2; p++) {
            u64t w0 = *(const u64t*)(B0 +k+2*p);
            u64t w1 = *(const u64t*)(B1p+k+2*p);
            u64t w2 = *(const u64t*)(B2p+k+2*p);
            u64t w3 = *(const u64t*)(B3p+k+2*p);
            acc[0][0]=f2fma(a0.u[p],w0,acc[0][0]); acc[0][1]=f2fma(a0.u[p],w1,acc[0][1]);
            acc[0][2]=f2fma(a0.u[p],w2,acc[0][2]); acc[0][3]=f2fma(a0.u[p],w3,acc[0][3]);
            acc[1][0]=f2fma(a1.u[p],w0,acc[1][0]); acc[1][1]=f2fma(a1.u[p],w1,acc[1][1]);
            acc[1][2]=f2fma(a1.u[p],w2,acc[1][2]); acc[1][3]=f2fma(a1.u[p],w3,acc[1][3]);
            acc[2][0]=f2fma(a2.u[p],w0,acc[2][0]); acc[2][1]=f2fma(a2.u[p],w1,acc[2][1]);
            acc[2][2]=f2fma(a2.u[p],w2,acc[2][2]); acc[2][3]=f2fma(a2.u[p],w3,acc[2][3]);
            acc[3][0]=f2fma(a3.u[p],w0,acc[3][0]); acc[3][1]=f2fma(a3.u[p],w1,acc[3][1]);
            acc[3][2]=f2fma(a3.u[p],w2,acc[3][2]); acc[3][3]=f2fma(a3.u[p],w3,acc[3][3]);
          }
        }
        float* pb = &g_p[(b*32 + r0)*256 + wc*64 + cg];
        #pragma unroll
        for (int r = 0; r < 4; r++)
          #pragma unroll
          for (int i = 0; i < 4; i++)
            pb[r*256 + 16*i] = f2fold(acc[r][i]);
      }
      gridbar();

      // ======== reduce partials -> k_s (each block: its 512 elements) =====
      {
        const int idL = slice*512 + tid;      // 0..8191 within slab
        const float* pp = &g_p[slab*16*8192 + idL];
        float sum = 0.f;
        #pragma unroll
        for (int sl = 0; sl < 16; sl++) sum += pp[sl*8192];
        sum += b2s[idL & 255];
        const int gi = slab*8192 + idL;

        if (s < 6) {
          g_k[(kbase + s) & 7][gi] = sum;
          gridbar();
        } else {
          // stage-6 fused with x5/err (k6 consumed in-register)
          g_k[(kbase + 6) & 7][gi] = sum;      // FSAL slot for next iteration
          float cb[7], cd[7];
          #pragma unroll
          for (int j = 0; j < 7; j++) { cb[j] = dt_c*c_B5[j]; cd[j] = dt_c*c_D[j]; }
          float x = cur[gi], x5 = x, err = 0.f;
          #pragma unroll
          for (int j = 0; j < 6; j++) {
            float kv = g_k[(kbase + j) & 7][gi];
            x5  = fmaf(cb[j], kv, x5);
            err = fmaf(cd[j], kv, err);
          }
          x5  = fmaf(cb[6], sum, x5);
          err = fmaf(cd[6], sum, err);
          nxt[gi] = x5;
          float scale = fmaf(1e-3f, fmaxf(fabsf(x), fabsf(x5)), 1e-4f);
          float r = err / scale;
          sA[tid] = r*r;
          __syncthreads();
          #pragma unroll
          for (int st = 256; st > 0; st >>= 1) {
            if (tid < st) sA[tid] += sA[tid + st];
            __syncthreads();
          }
          if (tid == 0) g_part[b] = sA[0];
        }
      }
    }
    gridbar();

    // ======== finalize (replicated in every block, identical fp) ==========
    {
      if (tid < NB) sA[tid] = g_part[tid];
      __syncthreads();
      #pragma unroll
      for (int st = 64; st > 0; st >>= 1) {
        if (tid < st) sA[tid] += sA[tid + st];
        __syncthreads();
      }
      float err_norm = sqrtf(sA[0] * (1.0f/(float)NX));
      __syncthreads();                          // protect sA[0] before reuse
      int accept = (err_norm <= 1.0f);
      float factor = 0.9f * powf(err_norm + 1e-10f, -0.2f);
      factor = fminf(fmaxf(factor, 0.2f), 5.0f);
      if (accept) { t = t + dt_c; par ^= 1; kbase = (kbase + 6) & 7; }
      dt = dt_c * factor;
      fsal = 1;   // k0 stays valid on reject too (x, t unchanged)
    }
  }

  // ---- write final trajectory row ----------------------------------------
  {
    int gi = slab*8192 + slice*512 + tid;
    out[NX + gi] = g_xbuf[par][gi];
  }
}

extern "C" void kernel_launch(void* const* d_in, const int* in_sizes, int n_in,
                              void* d_out, int out_size) {
  const float* x0 = (const float*)d_in[0];
  const float* W1 = (const float*)d_in[1];
  const float* b1 = (const float*)d_in[2];
  const float* W2 = (const float*)d_in[3];
  const float* b2 = (const float*)d_in[4];
  float* out = (float*)d_out;

  cudaFuncSetAttribute(k_ode, cudaFuncAttributeMaxDynamicSharedMemorySize, SMEM_BYTES);
  k_init<<<NB, NT>>>(x0, out);
  k_ode<<<NB, NT, SMEM_BYTES>>>(W1, b1, W2, b2, out);
}